// round 5
// baseline (speedup 1.0000x reference)
#include <cuda_runtime.h>
#include <cuda_bf16.h>
#include <cstdint>
#include <cstddef>

#define NB 4
#define NS 1024
#define ND 1024
#define NH 16
#define NHD 64
#define K3 3072            // 3 * 1024 : split-K packing (hi*hi + hi*lo + lo*hi)

// ---------------- scratch (allocation-free rule: __device__ globals) -------
__device__ float         g_qkv [(size_t)NB * NS * 3 * ND];     // 48 MB
__device__ float         g_attn[(size_t)NB * NS * ND];         // 16 MB
__device__ __nv_bfloat16 g_a3  [(size_t)NB * NS * K3];         // 25 MB  activations split
__device__ __nv_bfloat16 g_wc3t[(size_t)(3 * ND) * K3];        // 19 MB  Wc^T split
__device__ __nv_bfloat16 g_wp3t[(size_t)ND * K3];              //  6 MB  Wp^T split

// ---------------- PTX helpers (family-portable: no tcgen05) ----------------
__device__ __forceinline__ uint32_t smem_u32(const void* p) {
    uint32_t a;
    asm("{ .reg .u64 t; cvta.to.shared.u64 t, %1; cvt.u32.u64 %0, t; }" : "=r"(a) : "l"(p));
    return a;
}
__device__ __forceinline__ void ldm_x4(uint32_t* r, uint32_t addr) {
    asm volatile("ldmatrix.sync.aligned.m8n8.x4.shared.b16 {%0,%1,%2,%3}, [%4];"
                 : "=r"(r[0]), "=r"(r[1]), "=r"(r[2]), "=r"(r[3]) : "r"(addr));
}
__device__ __forceinline__ void mma16816(float* d, const uint32_t* a, const uint32_t* b) {
    asm volatile(
        "mma.sync.aligned.m16n8k16.row.col.f32.bf16.bf16.f32 "
        "{%0,%1,%2,%3}, {%4,%5,%6,%7}, {%8,%9}, {%0,%1,%2,%3};"
        : "+f"(d[0]), "+f"(d[1]), "+f"(d[2]), "+f"(d[3])
        : "r"(a[0]), "r"(a[1]), "r"(a[2]), "r"(a[3]), "r"(b[0]), "r"(b[1]));
}
#define CP_ASYNC16(smem, gmem) \
    asm volatile("cp.async.cg.shared.global [%0], [%1], 16;" :: "r"(smem), "l"(gmem) : "memory")
#define CP_COMMIT() asm volatile("cp.async.commit_group;" ::: "memory")
#define CP_WAIT1()  asm volatile("cp.async.wait_group 1;" ::: "memory")

__device__ __forceinline__ uint32_t sw128(uint32_t off) {   // XOR swizzle, 128B rows
    return off ^ ((off >> 3) & 0x70);
}

// ---------------------------------------------------------------------------
// Prep 1: split fp32 activations -> bf16 [M, 3K] = [hi | hi | lo]
// ---------------------------------------------------------------------------
__global__ void split_act(const float* __restrict__ in, __nv_bfloat16* __restrict__ out,
                          int M, int K)
{
    size_t i4 = ((size_t)blockIdx.x * blockDim.x + threadIdx.x) * 4;
    if (i4 >= (size_t)M * K) return;
    int r = (int)(i4 / K), c = (int)(i4 % K);
    float4 v = *(const float4*)(in + i4);
    float vv[4] = {v.x, v.y, v.z, v.w};
    __nv_bfloat16 hi[4], lo[4];
    #pragma unroll
    for (int j = 0; j < 4; j++) {
        hi[j] = __float2bfloat16(vv[j]);
        lo[j] = __float2bfloat16(vv[j] - __bfloat162float(hi[j]));
    }
    __nv_bfloat16* o = out + (size_t)r * (3 * K);
    *(__nv_bfloat162*)(o + c)             = __nv_bfloat162(hi[0], hi[1]);
    *(__nv_bfloat162*)(o + c + 2)         = __nv_bfloat162(hi[2], hi[3]);
    *(__nv_bfloat162*)(o + K + c)         = __nv_bfloat162(hi[0], hi[1]);
    *(__nv_bfloat162*)(o + K + c + 2)     = __nv_bfloat162(hi[2], hi[3]);
    *(__nv_bfloat162*)(o + 2 * K + c)     = __nv_bfloat162(lo[0], lo[1]);
    *(__nv_bfloat162*)(o + 2 * K + c + 2) = __nv_bfloat162(lo[2], lo[3]);
}

// ---------------------------------------------------------------------------
// Prep 2: transpose + split weights: W [K,N] fp32 -> Wt3 [N, 3K] bf16 = [hi | lo | hi]
// ---------------------------------------------------------------------------
__global__ void transpose_split(const float* __restrict__ W, __nv_bfloat16* __restrict__ Wt3,
                                int K, int N)
{
    __shared__ float t[32][33];
    int n0 = blockIdx.x * 32, k0 = blockIdx.y * 32;
    int tx = threadIdx.x, ty = threadIdx.y;
    #pragma unroll
    for (int i = 0; i < 32; i += 8)
        t[ty + i][tx] = W[(size_t)(k0 + ty + i) * N + n0 + tx];
    __syncthreads();
    #pragma unroll
    for (int i = 0; i < 32; i += 8) {
        float v = t[tx][ty + i];
        int n = n0 + ty + i, k = k0 + tx;
        __nv_bfloat16 hi = __float2bfloat16(v);
        __nv_bfloat16 lo = __float2bfloat16(v - __bfloat162float(hi));
        __nv_bfloat16* o = Wt3 + (size_t)n * (3 * K);
        o[k]         = hi;
        o[K + k]     = lo;
        o[2 * K + k] = hi;
    }
}

// ---------------------------------------------------------------------------
// bf16 tensor-core GEMM (mma.sync): C[M,N] = A3[M,K3] @ B3t[N,K3]^T + bias[N]
// Block 128x128, BK=64, 8 warps (4x2), warp tile 32x64, 3-stage cp.async.
// ---------------------------------------------------------------------------
#define BM 128
#define BN 128
#define BK 64
#define GT 256
#define KT (K3 / BK)                 // 48 k-tiles
#define STG_A     16384              // 128 rows x 128B
#define STG_BYTES 32768              // A + B per stage
#define SM_BIAS   (3 * STG_BYTES)    // 98304
#define SM_TOTAL  (SM_BIAS + BN * 4)

__global__ __launch_bounds__(GT, 2)
void gemm_mma(const __nv_bfloat16* __restrict__ A, const __nv_bfloat16* __restrict__ B,
              const float* __restrict__ bias, float* __restrict__ C, int N)
{
    extern __shared__ char smem[];
    const uint32_t sb = smem_u32(smem);
    const int tid  = threadIdx.x;
    const int wid  = tid >> 5;
    const int lane = tid & 31;
    const int m0 = blockIdx.y * BM, n0 = blockIdx.x * BN;
    const int warp_m = (wid & 3) * 32;
    const int warp_n = (wid >> 2) * 64;

    float* bias_s = (float*)(smem + SM_BIAS);
    for (int i = tid; i < BN; i += GT) bias_s[i] = bias[n0 + i];

    const char* Ag = (const char*)(A + (size_t)m0 * K3);
    const char* Bg = (const char*)(B + (size_t)n0 * K3);
    const size_t rowb = (size_t)K3 * 2;     // 6144 B per row
    // per-thread gmem chunk: row = tid>>3 (+32*i), 16B chunk c = tid&7
    const int lrow = tid >> 3, lc = (tid & 7) << 4;
    const uint32_t soff = sw128((uint32_t)(lrow * 128 + lc));

    auto load_stage = [&](int kt, int s) {
        const size_t goff = (size_t)lrow * rowb + (size_t)kt * 128 + lc;
        const uint32_t sa = sb + s * STG_BYTES + soff;
        const char* ga = Ag + goff;
        const char* gb = Bg + goff;
        #pragma unroll
        for (int i = 0; i < 4; i++) {
            CP_ASYNC16(sa + i * 4096,           ga + (size_t)i * 32 * rowb);
            CP_ASYNC16(sa + STG_A + i * 4096,   gb + (size_t)i * 32 * rowb);
        }
        CP_COMMIT();
    };

    load_stage(0, 0);
    load_stage(1, 1);

    float d[2][8][4];
    #pragma unroll
    for (int mt = 0; mt < 2; mt++)
        #pragma unroll
        for (int nt = 0; nt < 8; nt++)
            #pragma unroll
            for (int j = 0; j < 4; j++) d[mt][nt][j] = 0.f;

    const int sub = lane >> 3, lr = lane & 7;

    for (int kt = 0; kt < KT; kt++) {
        CP_WAIT1();
        __syncthreads();
        if (kt + 2 < KT) load_stage(kt + 2, (kt + 2) % 3);
        else             CP_COMMIT();            // keep group counting aligned

        const uint32_t a_base = sb + (kt % 3) * STG_BYTES;
        const uint32_t b_base = a_base + STG_A;

        #pragma unroll
        for (int ks = 0; ks < 4; ks++) {
            uint32_t af[2][4];
            #pragma unroll
            for (int mt = 0; mt < 2; mt++) {
                uint32_t off = (uint32_t)((warp_m + mt * 16 + (sub & 1) * 8 + lr) * 128
                                          + ks * 32 + (sub >> 1) * 16);
                ldm_x4(af[mt], a_base + sw128(off));
            }
            uint32_t bf[4][4];
            #pragma unroll
            for (int bt = 0; bt < 4; bt++) {
                uint32_t off = (uint32_t)((warp_n + bt * 16 + (sub >> 1) * 8 + lr) * 128
                                          + ks * 32 + (sub & 1) * 16);
                ldm_x4(bf[bt], b_base + sw128(off));
            }
            #pragma unroll
            for (int mt = 0; mt < 2; mt++)
                #pragma unroll
                for (int nt = 0; nt < 8; nt++)
                    mma16816(d[mt][nt], af[mt], &bf[nt >> 1][(nt & 1) * 2]);
        }
        __syncthreads();
    }

    // Epilogue: bias + fp32 stores (float2 per fragment pair).
    #pragma unroll
    for (int mt = 0; mt < 2; mt++) {
        const int r = m0 + warp_m + mt * 16 + (lane >> 2);
        #pragma unroll
        for (int nt = 0; nt < 8; nt++) {
            const int c = warp_n + nt * 8 + (lane & 3) * 2;
            const float bx = bias_s[c], by = bias_s[c + 1];
            float2 v0 = make_float2(d[mt][nt][0] + bx, d[mt][nt][1] + by);
            float2 v1 = make_float2(d[mt][nt][2] + bx, d[mt][nt][3] + by);
            *(float2*)(C + (size_t)r * N + n0 + c)       = v0;
            *(float2*)(C + (size_t)(r + 8) * N + n0 + c) = v1;
        }
    }
}

// ---------------------------------------------------------------------------
// Fused attention (unchanged — fp32, flash style).
// ---------------------------------------------------------------------------
#define ATTN_SMEM_FLOATS (64*64 + 64*66 + 64*64 + 64*64)
#define ATTN_SMEM_BYTES  (ATTN_SMEM_FLOATS * 4)

__global__ __launch_bounds__(512, 2)
void attn_kernel(const float* __restrict__ qkv,
                 const float* __restrict__ tk,
                 const float* __restrict__ tv,
                 float* __restrict__ out)
{
    extern __shared__ float sm[];
    float* Qs = sm;
    float* Kt = sm + 64 * 64;
    float* Vs = Kt + 64 * 66;
    float* Ps = Vs + 64 * 64;

    const int stile = blockIdx.x;
    const int bh    = blockIdx.y;
    const int b     = bh >> 4;
    const int h     = bh & 15;
    const int q0    = stile * 64;
    const int tid   = threadIdx.x;
    const int w     = tid >> 5;
    const int lane  = tid & 31;

    for (int idx = tid; idx < 64 * 64; idx += 512) {
        int r = idx >> 6, dd = idx & 63;
        Qs[r * 64 + dd] = qkv[(size_t)(b * NS + q0 + r) * (3 * ND) + h * NHD + dd];
    }
    __syncthreads();

    const float scale = 0.125f;
    float m[4], l[4], sself[4], acc0[4], acc1[4];

    #pragma unroll
    for (int r = 0; r < 4; r++) {
        int row = w * 4 + r;
        const float* kp = qkv + (size_t)(b * NS + q0 + row) * (3 * ND) + ND + h * NHD;
        float2 kv = *(const float2*)(kp + 2 * lane);
        float part = Qs[row * 64 + 2 * lane] * kv.x + Qs[row * 64 + 2 * lane + 1] * kv.y;
        #pragma unroll
        for (int off = 16; off; off >>= 1)
            part += __shfl_xor_sync(0xffffffffu, part, off);
        sself[r] = part * scale;
        m[r] = sself[r]; l[r] = 1.f; acc0[r] = 0.f; acc1[r] = 0.f;
    }

    const float* tkb = tk + (size_t)bh * NS * NHD;
    const float* tvb = tv + (size_t)bh * NS * NHD;

    for (int t = 0; t <= stile; t++) {
        __syncthreads();
        for (int idx = tid; idx < 64 * 64; idx += 512) {
            int j = idx >> 6, dd = idx & 63;
            size_t goff = (size_t)(t * 64 + j) * NHD + dd;
            Kt[dd * 66 + j] = tkb[goff];
            Vs[idx]         = tvb[goff];
        }
        __syncthreads();

        float sa[4] = {0, 0, 0, 0}, sb2[4] = {0, 0, 0, 0};
        #pragma unroll
        for (int d0 = 0; d0 < 64; d0 += 4) {
            float qv[4][4];
            #pragma unroll
            for (int r = 0; r < 4; r++)
                *(float4*)qv[r] = *(const float4*)(Qs + (w * 4 + r) * 64 + d0);
            #pragma unroll
            for (int dd = 0; dd < 4; dd++) {
                float2 kk = *(const float2*)(Kt + (d0 + dd) * 66 + 2 * lane);
                #pragma unroll
                for (int r = 0; r < 4; r++) {
                    sa[r]  = fmaf(qv[r][dd], kk.x, sa[r]);
                    sb2[r] = fmaf(qv[r][dd], kk.y, sb2[r]);
                }
            }
        }

        const bool diag = (t == stile);
        #pragma unroll
        for (int r = 0; r < 4; r++) {
            int row = w * 4 + r;
            float va = sa[r] * scale, vb = sb2[r] * scale;
            if (diag) {
                if (2 * lane     >= row) va = -1e30f;
                if (2 * lane + 1 >= row) vb = -1e30f;
            }
            float tmx = fmaxf(va, vb);
            #pragma unroll
            for (int off = 16; off; off >>= 1)
                tmx = fmaxf(tmx, __shfl_xor_sync(0xffffffffu, tmx, off));
            float mnew = fmaxf(m[r], tmx);
            float corr = __expf(m[r] - mnew);
            float pa = __expf(va - mnew);
            float pb = __expf(vb - mnew);
            float ps = pa + pb;
            #pragma unroll
            for (int off = 16; off; off >>= 1)
                ps += __shfl_xor_sync(0xffffffffu, ps, off);
            l[r] = l[r] * corr + ps;
            m[r] = mnew;
            acc0[r] *= corr;
            acc1[r] *= corr;
            *(float2*)(Ps + (w * 4 + r) * 64 + 2 * lane) = make_float2(pa, pb);
        }
        __syncwarp();

        #pragma unroll 2
        for (int j0 = 0; j0 < 64; j0 += 4) {
            float pr[4][4];
            #pragma unroll
            for (int r = 0; r < 4; r++)
                *(float4*)pr[r] = *(const float4*)(Ps + (w * 4 + r) * 64 + j0);
            #pragma unroll
            for (int jj = 0; jj < 4; jj++) {
                float2 vv = *(const float2*)(Vs + (j0 + jj) * 64 + 2 * lane);
                #pragma unroll
                for (int r = 0; r < 4; r++) {
                    acc0[r] = fmaf(pr[r][jj], vv.x, acc0[r]);
                    acc1[r] = fmaf(pr[r][jj], vv.y, acc1[r]);
                }
            }
        }
    }

    #pragma unroll
    for (int r = 0; r < 4; r++) {
        int row = w * 4 + r;
        float inv   = 1.f / l[r];
        float wself = __expf(sself[r] - m[r]) * inv;
        const float* vp = qkv + (size_t)(b * NS + q0 + row) * (3 * ND) + 2 * ND + h * NHD;
        float2 vv = *(const float2*)(vp + 2 * lane);
        float o0 = acc0[r] * inv + wself * vv.x;
        float o1 = acc1[r] * inv + wself * vv.y;
        *(float2*)(out + (size_t)(b * NS + q0 + row) * ND + h * NHD + 2 * lane) =
            make_float2(o0, o1);
    }
}

// ---------------------------------------------------------------------------
extern "C" void kernel_launch(void* const* d_in, const int* in_sizes, int n_in,
                              void* d_out, int out_size)
{
    const float* hs = (const float*)d_in[0];
    const float* tk = (const float*)d_in[1];
    const float* tv = (const float*)d_in[2];
    const float* Wc = (const float*)d_in[3];
    const float* bc = (const float*)d_in[4];
    const float* Wp = (const float*)d_in[5];
    const float* bp = (const float*)d_in[6];
    float* out = (float*)d_out;

    float *qkv, *attn;
    __nv_bfloat16 *a3, *wc3t, *wp3t;
    cudaGetSymbolAddress((void**)&qkv,  g_qkv);
    cudaGetSymbolAddress((void**)&attn, g_attn);
    cudaGetSymbolAddress((void**)&a3,   g_a3);
    cudaGetSymbolAddress((void**)&wc3t, g_wc3t);
    cudaGetSymbolAddress((void**)&wp3t, g_wp3t);

    cudaFuncSetAttribute(gemm_mma, cudaFuncAttributeMaxDynamicSharedMemorySize, SM_TOTAL);
    cudaFuncSetAttribute(attn_kernel, cudaFuncAttributeMaxDynamicSharedMemorySize, ATTN_SMEM_BYTES);

    const int MROWS = NB * NS;   // 4096

    // Prep: split activations + transpose/split both weight matrices.
    split_act<<<(MROWS * ND / 4 + 255) / 256, 256>>>(hs, a3, MROWS, ND);
    transpose_split<<<dim3(3 * ND / 32, ND / 32), dim3(32, 8)>>>(Wc, wc3t, ND, 3 * ND);
    transpose_split<<<dim3(ND / 32, ND / 32), dim3(32, 8)>>>(Wp, wp3t, ND, ND);

    // 1) QKV projection (tensor cores): [4096,3072] = A3 @ Wc3t^T
    gemm_mma<<<dim3(3 * ND / BN, MROWS / BM), GT, SM_TOTAL>>>(a3, wc3t, bc, qkv, 3 * ND);

    // 2) Fused causal attention + self slot
    attn_kernel<<<dim3(NS / 64, NB * NH), 512, ATTN_SMEM_BYTES>>>(qkv, tk, tv, attn);

    // 3) Output projection (tensor cores)
    split_act<<<(MROWS * ND / 4 + 255) / 256, 256>>>(attn, a3, MROWS, ND);
    gemm_mma<<<dim3(ND / BN, MROWS / BM), GT, SM_TOTAL>>>(a3, wp3t, bp, out, ND);
}

// round 6
// speedup vs baseline: 3.7698x; 3.7698x over previous
#include <cuda_runtime.h>
#include <cuda_fp16.h>
#include <cstdint>
#include <cstddef>

#define NB 4
#define NS 1024
#define ND 1024
#define NH 16
#define NHD 64
#define KD 1024

// ---------------- scratch (allocation-free rule: __device__ globals) -------
__device__ __half g_h16  [(size_t)NB * NS * ND];          //  8 MB hidden fp16
__device__ __half g_qkv16[(size_t)NB * NS * 3 * ND];      // 24 MB qkv fp16
__device__ __half g_attn16[(size_t)NB * NS * ND];         //  8 MB attn out fp16
__device__ __half g_wc16 [(size_t)(3 * ND) * ND];         //  6 MB Wc^T fp16
__device__ __half g_wp16 [(size_t)ND * ND];               //  2 MB Wp^T fp16
__device__ __half g_k16  [(size_t)NB * NH * NS * NHD];    //  8 MB textual_key fp16
__device__ __half g_v16  [(size_t)NB * NH * NS * NHD];    //  8 MB textual_value fp16

// ---------------- PTX helpers (family-portable) -----------------------------
__device__ __forceinline__ uint32_t smem_u32(const void* p) {
    uint32_t a;
    asm("{ .reg .u64 t; cvta.to.shared.u64 t, %1; cvt.u32.u64 %0, t; }" : "=r"(a) : "l"(p));
    return a;
}
__device__ __forceinline__ void ldm_x4(uint32_t* r, uint32_t addr) {
    asm volatile("ldmatrix.sync.aligned.m8n8.x4.shared.b16 {%0,%1,%2,%3}, [%4];"
                 : "=r"(r[0]), "=r"(r[1]), "=r"(r[2]), "=r"(r[3]) : "r"(addr));
}
__device__ __forceinline__ void ldm_x4_t(uint32_t* r, uint32_t addr) {
    asm volatile("ldmatrix.sync.aligned.m8n8.x4.trans.shared.b16 {%0,%1,%2,%3}, [%4];"
                 : "=r"(r[0]), "=r"(r[1]), "=r"(r[2]), "=r"(r[3]) : "r"(addr));
}
__device__ __forceinline__ void mma16816(float* d, const uint32_t* a, const uint32_t* b) {
    asm volatile(
        "mma.sync.aligned.m16n8k16.row.col.f32.f16.f16.f32 "
        "{%0,%1,%2,%3}, {%4,%5,%6,%7}, {%8,%9}, {%0,%1,%2,%3};"
        : "+f"(d[0]), "+f"(d[1]), "+f"(d[2]), "+f"(d[3])
        : "r"(a[0]), "r"(a[1]), "r"(a[2]), "r"(a[3]), "r"(b[0]), "r"(b[1]));
}
#define CP_ASYNC16(smem, gmem) \
    asm volatile("cp.async.cg.shared.global [%0], [%1], 16;" :: "r"(smem), "l"(gmem) : "memory")
#define CP_COMMIT() asm volatile("cp.async.commit_group;" ::: "memory")
#define CP_WAIT1()  asm volatile("cp.async.wait_group 1;" ::: "memory")
#define CP_WAIT0()  asm volatile("cp.async.wait_group 0;" ::: "memory")

__device__ __forceinline__ uint32_t sw128(uint32_t off) {   // XOR swizzle, 128B rows
    return off ^ ((off >> 3) & 0x70);
}

// ---------------------------------------------------------------------------
// Prep: fp32 -> fp16 convert (n % 4 == 0)
// ---------------------------------------------------------------------------
__global__ void f2h(const float* __restrict__ in, __half* __restrict__ out, int n)
{
    int i4 = (blockIdx.x * blockDim.x + threadIdx.x) * 4;
    if (i4 >= n) return;
    float4 v = *(const float4*)(in + i4);
    __half2 h0 = __floats2half2_rn(v.x, v.y);
    __half2 h1 = __floats2half2_rn(v.z, v.w);
    uint2 pk = make_uint2(*(uint32_t*)&h0, *(uint32_t*)&h1);
    *(uint2*)(out + i4) = pk;
}

// ---------------------------------------------------------------------------
// Prep: transpose W [K,N] fp32 -> Wt [N,K] fp16
// ---------------------------------------------------------------------------
__global__ void transpose_h(const float* __restrict__ W, __half* __restrict__ Wt,
                            int K, int N)
{
    __shared__ float t[32][33];
    int n0 = blockIdx.x * 32, k0 = blockIdx.y * 32;
    int tx = threadIdx.x, ty = threadIdx.y;
    #pragma unroll
    for (int i = 0; i < 32; i += 8)
        t[ty + i][tx] = W[(size_t)(k0 + ty + i) * N + n0 + tx];
    __syncthreads();
    #pragma unroll
    for (int i = 0; i < 32; i += 8)
        Wt[(size_t)(n0 + ty + i) * K + k0 + tx] = __float2half(t[tx][ty + i]);
}

// ---------------------------------------------------------------------------
// fp16 tensor-core GEMM: C[M,N] = A[M,K] @ Bt[N,K]^T + bias[N]
// Block 128x128, BK=64, 8 warps (4x2), warp tile 32x64, 3-stage cp.async.
// OutT = __half (no-bias-needed fp16 path still adds bias) or float.
// ---------------------------------------------------------------------------
#define GT 256
#define STG_A     16384              // 128 rows x 128B
#define STG_BYTES 32768
#define SM_BIAS   (3 * STG_BYTES)
#define SM_TOTAL  (SM_BIAS + 128 * 4)

template<typename OutT>
__global__ __launch_bounds__(GT, 2)
void gemm_mma(const __half* __restrict__ A, const __half* __restrict__ B,
              const float* __restrict__ bias, OutT* __restrict__ C, int N, int K)
{
    extern __shared__ char smem[];
    const uint32_t sb = smem_u32(smem);
    const int tid  = threadIdx.x;
    const int wid  = tid >> 5;
    const int lane = tid & 31;
    const int m0 = blockIdx.y * 128, n0 = blockIdx.x * 128;
    const int warp_m = (wid & 3) * 32;
    const int warp_n = (wid >> 2) * 64;
    const int KT = K / 64;

    float* bias_s = (float*)(smem + SM_BIAS);
    for (int i = tid; i < 128; i += GT) bias_s[i] = bias[n0 + i];

    const char* Ag = (const char*)(A + (size_t)m0 * K);
    const char* Bg = (const char*)(B + (size_t)n0 * K);
    const size_t rowb = (size_t)K * 2;
    const int lrow = tid >> 3, lc = (tid & 7) << 4;
    const uint32_t soff = sw128((uint32_t)(lrow * 128 + lc));

    auto load_stage = [&](int kt, int s) {
        const size_t goff = (size_t)lrow * rowb + (size_t)kt * 128 + lc;
        const uint32_t sa = sb + s * STG_BYTES + soff;
        const char* ga = Ag + goff;
        const char* gb = Bg + goff;
        #pragma unroll
        for (int i = 0; i < 4; i++) {
            CP_ASYNC16(sa + i * 4096,         ga + (size_t)i * 32 * rowb);
            CP_ASYNC16(sa + STG_A + i * 4096, gb + (size_t)i * 32 * rowb);
        }
        CP_COMMIT();
    };

    load_stage(0, 0);
    load_stage(1, 1);

    float d[2][8][4];
    #pragma unroll
    for (int mt = 0; mt < 2; mt++)
        #pragma unroll
        for (int nt = 0; nt < 8; nt++)
            #pragma unroll
            for (int j = 0; j < 4; j++) d[mt][nt][j] = 0.f;

    const int sub = lane >> 3, lr = lane & 7;

    for (int kt = 0; kt < KT; kt++) {
        CP_WAIT1();
        __syncthreads();
        if (kt + 2 < KT) load_stage(kt + 2, (kt + 2) % 3);
        else             CP_COMMIT();

        const uint32_t a_base = sb + (kt % 3) * STG_BYTES;
        const uint32_t b_base = a_base + STG_A;

        #pragma unroll
        for (int ks = 0; ks < 4; ks++) {
            uint32_t af[2][4];
            #pragma unroll
            for (int mt = 0; mt < 2; mt++) {
                uint32_t off = (uint32_t)((warp_m + mt * 16 + (sub & 1) * 8 + lr) * 128
                                          + ks * 32 + (sub >> 1) * 16);
                ldm_x4(af[mt], a_base + sw128(off));
            }
            uint32_t bf[4][4];
            #pragma unroll
            for (int bt = 0; bt < 4; bt++) {
                uint32_t off = (uint32_t)((warp_n + bt * 16 + (sub >> 1) * 8 + lr) * 128
                                          + ks * 32 + (sub & 1) * 16);
                ldm_x4(bf[bt], b_base + sw128(off));
            }
            #pragma unroll
            for (int mt = 0; mt < 2; mt++)
                #pragma unroll
                for (int nt = 0; nt < 8; nt++)
                    mma16816(d[mt][nt], af[mt], &bf[nt >> 1][(nt & 1) * 2]);
        }
        __syncthreads();
    }

    #pragma unroll
    for (int mt = 0; mt < 2; mt++) {
        const int r = m0 + warp_m + mt * 16 + (lane >> 2);
        #pragma unroll
        for (int nt = 0; nt < 8; nt++) {
            const int c = warp_n + nt * 8 + (lane & 3) * 2;
            const float bx = bias_s[c], by = bias_s[c + 1];
            if constexpr (sizeof(OutT) == 2) {
                __half2 v0 = __floats2half2_rn(d[mt][nt][0] + bx, d[mt][nt][1] + by);
                __half2 v1 = __floats2half2_rn(d[mt][nt][2] + bx, d[mt][nt][3] + by);
                *(__half2*)((__half*)C + (size_t)r * N + n0 + c)       = v0;
                *(__half2*)((__half*)C + (size_t)(r + 8) * N + n0 + c) = v1;
            } else {
                float2 v0 = make_float2(d[mt][nt][0] + bx, d[mt][nt][1] + by);
                float2 v1 = make_float2(d[mt][nt][2] + bx, d[mt][nt][3] + by);
                *(float2*)((float*)C + (size_t)r * N + n0 + c)       = v0;
                *(float2*)((float*)C + (size_t)(r + 8) * N + n0 + c) = v1;
            }
        }
    }
}

// ---------------------------------------------------------------------------
// Tensor-core flash attention, fp16 mma, 4 warps, 64 queries/block.
// Q pre-scaled fragments in registers; K non-trans ldmatrix; V trans ldmatrix;
// P repacked C-frag -> A-frag in registers. Self slot seeds online softmax.
// ---------------------------------------------------------------------------
#define ASM_Q    0
#define ASM_K    8192
#define ASM_V    24576
#define ASM_SELF 40960
#define ASM_TOTAL 41216

__global__ __launch_bounds__(128)
void attn_mma(const __half* __restrict__ qkv, const __half* __restrict__ kh,
              const __half* __restrict__ vh, __half* __restrict__ out)
{
    extern __shared__ char smem[];
    const uint32_t sb = smem_u32(smem);
    const int tid = threadIdx.x, warp = tid >> 5, lane = tid & 31;
    const int stile = gridDim.x - 1 - blockIdx.x;    // heavy tiles first
    const int bh = blockIdx.y, b = bh >> 4, h = bh & 15;
    const int q0 = stile * 64;
    float* sself = (float*)(smem + ASM_SELF);

    const __half* qbase = qkv + (size_t)(b * NS + q0) * (3 * ND) + h * NHD;
    const __half* kvK = kh + (size_t)bh * NS * NHD;
    const __half* kvV = vh + (size_t)bh * NS * NHD;

    // Q tile: 64 rows x 128B, cp.async
    #pragma unroll
    for (int i = 0; i < 4; i++) {
        int id = tid + i * 128, row = id >> 3, c = (id & 7) * 16;
        CP_ASYNC16(sb + ASM_Q + sw128((uint32_t)(row * 128 + c)),
                   (const char*)(qbase + (size_t)row * (3 * ND)) + c);
    }
    // K/V tile loader
    auto load_kv = [&](int t, int buf) {
        #pragma unroll
        for (int i = 0; i < 4; i++) {
            int id = tid + i * 128, row = id >> 3, c = (id & 7) * 16;
            uint32_t so = sw128((uint32_t)(row * 128 + c));
            CP_ASYNC16(sb + ASM_K + buf * 8192 + so,
                       (const char*)(kvK + (size_t)(t * 64 + row) * NHD) + c);
            CP_ASYNC16(sb + ASM_V + buf * 8192 + so,
                       (const char*)(kvV + (size_t)(t * 64 + row) * NHD) + c);
        }
    };
    load_kv(0, 0);
    CP_COMMIT();

    // Self logits (direct gmem; overlaps cp.async)
    for (int i = 0; i < 16; i++) {
        int row = warp * 16 + i;
        const __half* qp = qbase + (size_t)row * (3 * ND);
        float2 q2 = __half22float2(*(const __half2*)(qp + 2 * lane));
        float2 k2 = __half22float2(*(const __half2*)(qp + ND + 2 * lane));
        float dd = q2.x * k2.x + q2.y * k2.y;
        #pragma unroll
        for (int off = 16; off; off >>= 1)
            dd += __shfl_xor_sync(0xffffffffu, dd, off);
        if (lane == 0) sself[row] = dd * 0.125f;
    }

    const int r0 = lane >> 2;
    float m0, m1, l0 = 1.f, l1 = 1.f, sv0, sv1;
    float o[8][4];
    #pragma unroll
    for (int nt = 0; nt < 8; nt++)
        #pragma unroll
        for (int j = 0; j < 4; j++) o[nt][j] = 0.f;
    uint32_t aQ[4][4];

    for (int t = 0; t <= stile; t++) {
        if (t < stile) { load_kv(t + 1, (t + 1) & 1); CP_COMMIT(); CP_WAIT1(); }
        else           { CP_WAIT0(); }
        __syncthreads();

        if (t == 0) {
            const __half2 sc = __float2half2_rn(0.125f);
            #pragma unroll
            for (int ks = 0; ks < 4; ks++) {
                uint32_t addr = sb + ASM_Q +
                    sw128((uint32_t)((warp * 16 + (lane & 15)) * 128 + ks * 32 + (lane >> 4) * 16));
                ldm_x4(aQ[ks], addr);
                #pragma unroll
                for (int j = 0; j < 4; j++) {
                    __half2 hv = __hmul2(*(__half2*)&aQ[ks][j], sc);
                    aQ[ks][j] = *(uint32_t*)&hv;
                }
            }
            sv0 = sself[warp * 16 + r0];
            sv1 = sself[warp * 16 + r0 + 8];
            m0 = sv0; m1 = sv1;
        }

        const uint32_t kb = sb + ASM_K + (t & 1) * 8192;
        const uint32_t vb = sb + ASM_V + (t & 1) * 8192;

        // S = (Q/8) K^T
        float s[8][4];
        #pragma unroll
        for (int nt = 0; nt < 8; nt++)
            #pragma unroll
            for (int j = 0; j < 4; j++) s[nt][j] = 0.f;
        #pragma unroll
        for (int ks = 0; ks < 4; ks++) {
            #pragma unroll
            for (int kt2 = 0; kt2 < 4; kt2++) {
                uint32_t bf[4];
                uint32_t addr = kb + sw128((uint32_t)(
                    (kt2 * 16 + ((lane >> 4) & 1) * 8 + (lane & 7)) * 128
                    + ks * 32 + ((lane >> 3) & 1) * 16));
                ldm_x4(bf, addr);
                mma16816(s[2 * kt2],     aQ[ks], bf);
                mma16816(s[2 * kt2 + 1], aQ[ks], bf + 2);
            }
        }

        // Strict causal mask on diagonal tile (attend iff key < query)
        if (t == stile) {
            const int qr0 = warp * 16 + r0;
            #pragma unroll
            for (int nt = 0; nt < 8; nt++) {
                int kc = nt * 8 + 2 * (lane & 3);
                if (kc     >= qr0)     s[nt][0] = -1e30f;
                if (kc + 1 >= qr0)     s[nt][1] = -1e30f;
                if (kc     >= qr0 + 8) s[nt][2] = -1e30f;
                if (kc + 1 >= qr0 + 8) s[nt][3] = -1e30f;
            }
        }

        // Online softmax
        float mx0 = -1e30f, mx1 = -1e30f;
        #pragma unroll
        for (int nt = 0; nt < 8; nt++) {
            mx0 = fmaxf(mx0, fmaxf(s[nt][0], s[nt][1]));
            mx1 = fmaxf(mx1, fmaxf(s[nt][2], s[nt][3]));
        }
        #pragma unroll
        for (int off = 1; off < 4; off <<= 1) {
            mx0 = fmaxf(mx0, __shfl_xor_sync(0xffffffffu, mx0, off));
            mx1 = fmaxf(mx1, __shfl_xor_sync(0xffffffffu, mx1, off));
        }
        float mn0 = fmaxf(m0, mx0), mn1 = fmaxf(m1, mx1);
        float c0 = __expf(m0 - mn0), c1 = __expf(m1 - mn1);
        float ps0 = 0.f, ps1 = 0.f;
        #pragma unroll
        for (int nt = 0; nt < 8; nt++) {
            s[nt][0] = __expf(s[nt][0] - mn0);
            s[nt][1] = __expf(s[nt][1] - mn0);
            s[nt][2] = __expf(s[nt][2] - mn1);
            s[nt][3] = __expf(s[nt][3] - mn1);
            ps0 += s[nt][0] + s[nt][1];
            ps1 += s[nt][2] + s[nt][3];
        }
        #pragma unroll
        for (int off = 1; off < 4; off <<= 1) {
            ps0 += __shfl_xor_sync(0xffffffffu, ps0, off);
            ps1 += __shfl_xor_sync(0xffffffffu, ps1, off);
        }
        l0 = l0 * c0 + ps0;
        l1 = l1 * c1 + ps1;
        m0 = mn0; m1 = mn1;
        #pragma unroll
        for (int nt = 0; nt < 8; nt++) {
            o[nt][0] *= c0; o[nt][1] *= c0;
            o[nt][2] *= c1; o[nt][3] *= c1;
        }

        // O += P V
        #pragma unroll
        for (int ks = 0; ks < 4; ks++) {
            uint32_t aP[4];
            __half2 ph;
            ph = __floats2half2_rn(s[2 * ks][0],     s[2 * ks][1]);     aP[0] = *(uint32_t*)&ph;
            ph = __floats2half2_rn(s[2 * ks][2],     s[2 * ks][3]);     aP[1] = *(uint32_t*)&ph;
            ph = __floats2half2_rn(s[2 * ks + 1][0], s[2 * ks + 1][1]); aP[2] = *(uint32_t*)&ph;
            ph = __floats2half2_rn(s[2 * ks + 1][2], s[2 * ks + 1][3]); aP[3] = *(uint32_t*)&ph;
            #pragma unroll
            for (int dt = 0; dt < 4; dt++) {
                uint32_t bv[4];
                uint32_t addr = vb + sw128((uint32_t)(
                    (ks * 16 + ((lane >> 3) & 1) * 8 + (lane & 7)) * 128
                    + dt * 32 + ((lane >> 4) & 1) * 16));
                ldm_x4_t(bv, addr);
                mma16816(o[2 * dt],     aP, bv);
                mma16816(o[2 * dt + 1], aP, bv + 2);
            }
        }
        __syncthreads();
    }

    // Epilogue: normalize, add self-value, write fp16
    float inv0 = 1.f / l0, inv1 = 1.f / l1;
    float w0 = __expf(sv0 - m0) * inv0, w1 = __expf(sv1 - m1) * inv1;
    const int grow = q0 + warp * 16 + r0;
    const __half* v0p = qkv + (size_t)(b * NS + grow) * (3 * ND) + 2 * ND + h * NHD;
    const __half* v1p = v0p + (size_t)8 * (3 * ND);
    __half* o0p = out + (size_t)(b * NS + grow) * ND + h * NHD;
    __half* o1p = o0p + (size_t)8 * ND;
    #pragma unroll
    for (int nt = 0; nt < 8; nt++) {
        int col = nt * 8 + 2 * (lane & 3);
        float2 vv0 = __half22float2(*(const __half2*)(v0p + col));
        float2 vv1 = __half22float2(*(const __half2*)(v1p + col));
        __half2 r0h = __floats2half2_rn(o[nt][0] * inv0 + w0 * vv0.x,
                                        o[nt][1] * inv0 + w0 * vv0.y);
        __half2 r1h = __floats2half2_rn(o[nt][2] * inv1 + w1 * vv1.x,
                                        o[nt][3] * inv1 + w1 * vv1.y);
        *(__half2*)(o0p + col) = r0h;
        *(__half2*)(o1p + col) = r1h;
    }
}

// ---------------------------------------------------------------------------
extern "C" void kernel_launch(void* const* d_in, const int* in_sizes, int n_in,
                              void* d_out, int out_size)
{
    const float* hs = (const float*)d_in[0];
    const float* tk = (const float*)d_in[1];
    const float* tv = (const float*)d_in[2];
    const float* Wc = (const float*)d_in[3];
    const float* bc = (const float*)d_in[4];
    const float* Wp = (const float*)d_in[5];
    const float* bp = (const float*)d_in[6];
    float* out = (float*)d_out;

    __half *h16, *qkv16, *attn16, *wc16, *wp16, *k16, *v16;
    cudaGetSymbolAddress((void**)&h16,    g_h16);
    cudaGetSymbolAddress((void**)&qkv16,  g_qkv16);
    cudaGetSymbolAddress((void**)&attn16, g_attn16);
    cudaGetSymbolAddress((void**)&wc16,   g_wc16);
    cudaGetSymbolAddress((void**)&wp16,   g_wp16);
    cudaGetSymbolAddress((void**)&k16,    g_k16);
    cudaGetSymbolAddress((void**)&v16,    g_v16);

    cudaFuncSetAttribute(gemm_mma<__half>, cudaFuncAttributeMaxDynamicSharedMemorySize, SM_TOTAL);
    cudaFuncSetAttribute(gemm_mma<float>,  cudaFuncAttributeMaxDynamicSharedMemorySize, SM_TOTAL);
    cudaFuncSetAttribute(attn_mma, cudaFuncAttributeMaxDynamicSharedMemorySize, ASM_TOTAL);

    const int MROWS = NB * NS;            // 4096
    const int NKV   = NB * NH * NS * NHD; // 4194304

    // Preps: fp16 conversions + weight transposes
    f2h<<<(MROWS * ND / 4 + 255) / 256, 256>>>(hs, h16, MROWS * ND);
    f2h<<<(NKV / 4 + 255) / 256, 256>>>(tk, k16, NKV);
    f2h<<<(NKV / 4 + 255) / 256, 256>>>(tv, v16, NKV);
    transpose_h<<<dim3(3 * ND / 32, ND / 32), dim3(32, 8)>>>(Wc, wc16, ND, 3 * ND);
    transpose_h<<<dim3(ND / 32, ND / 32), dim3(32, 8)>>>(Wp, wp16, ND, ND);

    // 1) QKV projection (fp16 out)
    gemm_mma<__half><<<dim3(3 * ND / 128, MROWS / 128), GT, SM_TOTAL>>>(
        h16, wc16, bc, qkv16, 3 * ND, KD);

    // 2) Tensor-core flash attention (fp16 out)
    attn_mma<<<dim3(NS / 64, NB * NH), 128, ASM_TOTAL>>>(qkv16, k16, v16, attn16);

    // 3) Output projection (fp32 out)
    gemm_mma<float><<<dim3(ND / 128, MROWS / 128), GT, SM_TOTAL>>>(
        attn16, wp16, bp, out, ND, KD);
}